// round 15
// baseline (speedup 1.0000x reference)
#include <cuda_runtime.h>
#include <cuda_bf16.h>
#include <math.h>
#include <stdint.h>

#define B_  2
#define S_  2048
#define H_  8
#define D_  64
#define DM_ 512
#define W_  128

// ---------------- scratch (device globals; no allocation) ------------------
__device__ __nv_bfloat16 g_qh[B_*H_*S_*D_];
__device__ __nv_bfloat16 g_ql[B_*H_*S_*D_];
__device__ __nv_bfloat16 g_kh[B_*H_*S_*D_];
__device__ __nv_bfloat16 g_kl[B_*H_*S_*D_];
__device__ __nv_bfloat16 g_vh[B_*H_*S_*D_];
__device__ __nv_bfloat16 g_vl[B_*H_*S_*D_];
__device__ __nv_bfloat16 g_ah[B_*S_*DM_];
__device__ __nv_bfloat16 g_al[B_*S_*DM_];
__device__ __nv_bfloat16 g_wh[4*DM_*DM_];     // W^T hi: rows 0..1535 Wq,Wk,Wv; 1536.. Wo
__device__ __nv_bfloat16 g_wl[4*DM_*DM_];     // W^T lo

__device__ __forceinline__ uint32_t smem_u32(const void* p) {
    uint32_t a;
    asm("{ .reg .u64 t; cvta.to.shared.u64 t, %1; cvt.u32.u64 %0, t; }" : "=r"(a) : "l"(p));
    return a;
}

// ---------------- mma.sync building blocks (plain sm_103 PTX) --------------
#define LDSM4(r, addr) \
    asm volatile("ldmatrix.sync.aligned.m8n8.x4.shared.b16 {%0,%1,%2,%3}, [%4];" \
        : "=r"((r)[0]), "=r"((r)[1]), "=r"((r)[2]), "=r"((r)[3]) : "r"(addr))

#define LDSM4T(r, addr) \
    asm volatile("ldmatrix.sync.aligned.m8n8.x4.trans.shared.b16 {%0,%1,%2,%3}, [%4];" \
        : "=r"((r)[0]), "=r"((r)[1]), "=r"((r)[2]), "=r"((r)[3]) : "r"(addr))

#define MMA16816(c, a, b0, b1) \
    asm volatile("mma.sync.aligned.m16n8k16.row.col.f32.bf16.bf16.f32 " \
        "{%0,%1,%2,%3}, {%4,%5,%6,%7}, {%8,%9}, {%0,%1,%2,%3};" \
        : "+f"((c)[0]), "+f"((c)[1]), "+f"((c)[2]), "+f"((c)[3]) \
        : "r"((a)[0]), "r"((a)[1]), "r"((a)[2]), "r"((a)[3]), "r"(b0), "r"(b1))

__device__ __forceinline__ void cpa16(uint32_t s, const __nv_bfloat16* g) {
    asm volatile("cp.async.ca.shared.global [%0], [%1], 16;" :: "r"(s), "l"(g));
}
__device__ __forceinline__ void cpa16z(uint32_t s, const __nv_bfloat16* g, uint32_t sz) {
    asm volatile("cp.async.ca.shared.global [%0], [%1], 16, %2;" :: "r"(s), "l"(g), "r"(sz));
}

__device__ __forceinline__ void split_bf16(float x, __nv_bfloat16& h, __nv_bfloat16& l) {
    h = __float2bfloat16(x);
    l = __float2bfloat16(x - __bfloat162float(h));
}
__device__ __forceinline__ uint32_t pkbf(__nv_bfloat16 x, __nv_bfloat16 y) {
    __nv_bfloat162 t(x, y);
    return *(uint32_t*)&t;
}

// ---------------------------------------------------------------------------
// Merged conversion kernel: blocks [0,2048) split X; [2048,3072) split+T W.
// ---------------------------------------------------------------------------
__global__ void __launch_bounds__(256) conv_k(const float* __restrict__ X,
                                              const float* __restrict__ Wq,
                                              const float* __restrict__ Wk,
                                              const float* __restrict__ Wv,
                                              const float* __restrict__ Wo)
{
    __shared__ float t[32][33];
    if (blockIdx.x < 2048) {
        int i = (blockIdx.x * 256 + threadIdx.x) * 4;
        float4 v = *(const float4*)(X + i);
        __nv_bfloat16 h0, h1, h2, h3, l0, l1, l2, l3;
        split_bf16(v.x, h0, l0); split_bf16(v.y, h1, l1);
        split_bf16(v.z, h2, l2); split_bf16(v.w, h3, l3);
        *(__nv_bfloat162*)(g_ah + i)     = __nv_bfloat162(h0, h1);
        *(__nv_bfloat162*)(g_ah + i + 2) = __nv_bfloat162(h2, h3);
        *(__nv_bfloat162*)(g_al + i)     = __nv_bfloat162(l0, l1);
        *(__nv_bfloat162*)(g_al + i + 2) = __nv_bfloat162(l2, l3);
        return;
    }
    int wi = blockIdx.x - 2048;
    int z  = wi >> 8;
    int bn = (wi & 15) * 32;
    int bk = ((wi >> 4) & 15) * 32;
    const float* Wsrc = (z == 0) ? Wq : (z == 1 ? Wk : (z == 2 ? Wv : Wo));
    int lx = threadIdx.x & 31, ly = threadIdx.x >> 5;
#pragma unroll
    for (int i = 0; i < 32; i += 8)
        t[ly + i][lx] = Wsrc[(bk + ly + i) * DM_ + bn + lx];
    __syncthreads();
    int rowbase = z * DM_;
#pragma unroll
    for (int i = 0; i < 32; i += 8) {
        int r = ly + i;
        float x = t[lx][r];
        __nv_bfloat16 h, l;
        split_bf16(x, h, l);
        long idx = (long)(rowbase + bn + r) * DM_ + bk + lx;
        g_wh[idx] = h;
        g_wl[idx] = l;
    }
}

// ---------------------------------------------------------------------------
// mma.sync split-bf16 GEMM, templated on BN (measured-best per projection):
//   qkv: BN=128 (stage 32KB, grid 384)     out: BN=64 (stage 24KB, grid 256)
// BM=128, BK=32, 256 threads, 8 warps (warp tile 32 x BN/2), 3-stage pipe.
// Stage layout: Ah[128] 8K | Al 8K | Bh[BN] BN*64 | Bl BN*64.
// Swizzled 64B rows: chunk' = (chunk + (row>>1)) & 3.
// ---------------------------------------------------------------------------
template<int BN>
__device__ __forceinline__ void stage_t(uint32_t sb, int st, int m0, int nbase, int k0)
{
    const int GSTAGE = 16384 + BN * 128;
    const int tid = threadIdx.x;
    uint32_t sbase = sb + st * GSTAGE;
#pragma unroll
    for (int i = 0; i < 2; i++) {
        int u = tid + (i << 8);
        int r = u >> 2, seg = u & 3;
        int sw = ((seg + (r >> 1)) & 3) * 16;
        uint32_t so = sbase + r * 64 + sw;
        long ga = (long)(m0 + r) * DM_ + k0 + seg * 8;
        cpa16(so,        g_ah + ga);
        cpa16(so + 8192, g_al + ga);
    }
#pragma unroll
    for (int i = 0; i < BN / 64; i++) {
        int u = tid + (i << 8);
        int r = u >> 2, seg = u & 3;
        int sw = ((seg + (r >> 1)) & 3) * 16;
        uint32_t so = sbase + 16384 + r * 64 + sw;
        long gb = (long)(nbase + r) * DM_ + k0 + seg * 8;
        cpa16(so,           g_wh + gb);
        cpa16(so + BN * 64, g_wl + gb);
    }
    asm volatile("cp.async.commit_group;" ::: "memory");
}

template<int BN>
__device__ __forceinline__ void compute_chunk_t(uint32_t sb, int st,
                                                float acc[2][BN/16][4])
{
    const int GSTAGE = 16384 + BN * 128;
    const int lane = threadIdx.x & 31, w = threadIdx.x >> 5;
    const int wM = (w & 3) * 32, wN = (w >> 2) * (BN / 2);
    uint32_t base = sb + st * GSTAGE;
    const int arow_ = wM + (lane & 15);
    const int ach = lane >> 4;                 // 0/1
    const int brow_ = wN + ((lane >> 4) ? 8 : 0) + (lane & 7);
    const int bch = (lane >> 3) & 1;

#pragma unroll
    for (int kk = 0; kk < 2; kk++) {
        uint32_t a_hi[2][4], a_lo[2][4];
#pragma unroll
        for (int mt = 0; mt < 2; mt++) {
            int row = arow_ + mt * 16;
            int ch = ((kk * 2 + ach + (row >> 1)) & 3) * 16;
            uint32_t ad = base + row * 64 + ch;
            LDSM4(a_hi[mt], ad);
            LDSM4(a_lo[mt], ad + 8192);
        }
#pragma unroll
        for (int nb = 0; nb < BN / 32; nb++) {
            int row = brow_ + nb * 16;
            int ch = ((kk * 2 + bch + (row >> 1)) & 3) * 16;
            uint32_t bd = base + 16384 + row * 64 + ch;
            uint32_t bh[4], bl[4];
            LDSM4(bh, bd);
            LDSM4(bl, bd + BN * 64);
#pragma unroll
            for (int mt = 0; mt < 2; mt++) {
                MMA16816(acc[mt][nb * 2 + 0], a_hi[mt], bh[0], bh[1]);
                MMA16816(acc[mt][nb * 2 + 0], a_hi[mt], bl[0], bl[1]);
                MMA16816(acc[mt][nb * 2 + 0], a_lo[mt], bh[0], bh[1]);
                MMA16816(acc[mt][nb * 2 + 1], a_hi[mt], bh[2], bh[3]);
                MMA16816(acc[mt][nb * 2 + 1], a_hi[mt], bl[2], bl[3]);
                MMA16816(acc[mt][nb * 2 + 1], a_lo[mt], bh[2], bh[3]);
            }
        }
    }
}

template<int BN>
__device__ __forceinline__ void gemm_mainloop_t(uint32_t sb, int m0, int nbase,
                                                float acc[2][BN/16][4])
{
#pragma unroll
    for (int mt = 0; mt < 2; mt++)
#pragma unroll
        for (int nf = 0; nf < BN / 16; nf++)
#pragma unroll
            for (int e = 0; e < 4; e++) acc[mt][nf][e] = 0.f;

    stage_t<BN>(sb, 0, m0, nbase, 0);
    stage_t<BN>(sb, 1, m0, nbase, 32);
    for (int c = 0; c < 16; c++) {
        if (c < 15) asm volatile("cp.async.wait_group 1;" ::: "memory");
        else        asm volatile("cp.async.wait_group 0;" ::: "memory");
        __syncthreads();
        compute_chunk_t<BN>(sb, c % 3, acc);
        if (c < 14) stage_t<BN>(sb, (c + 2) % 3, m0, nbase, (c + 2) * 32);
    }
}

// QKV projection: BN=128 (round-9 best shape), grid (12, 32).
__global__ void __launch_bounds__(256, 2) mma_gemm_qkv()
{
    extern __shared__ char sm[];
    uint32_t sb = smem_u32(sm);
    const int m0 = blockIdx.y << 7;
    const int nbase = blockIdx.x << 7;       // 0..1535
    float acc[2][8][4];
    gemm_mainloop_t<128>(sb, m0, nbase, acc);

    const int lane = threadIdx.x & 31, w = threadIdx.x >> 5;
    const int wM = (w & 3) * 32, wN = (w >> 2) * 64;
#pragma unroll
    for (int mt = 0; mt < 2; mt++) {
        int r0 = m0 + wM + mt * 16 + (lane >> 2);
        int b = r0 >> 11, s = r0 & (S_ - 1);
#pragma unroll
        for (int nb = 0; nb < 4; nb++) {
#pragma unroll
            for (int nf = 0; nf < 2; nf++) {
                float* c = acc[mt][nb * 2 + nf];
                int n = nbase + wN + nb * 16 + nf * 8 + (lane & 3) * 2;
                int mat = n >> 9, cc = n & 511;
                int h = cc >> 6, d = cc & 63;
                __nv_bfloat16* oh = (mat == 0) ? g_qh : (mat == 1 ? g_kh : g_vh);
                __nv_bfloat16* ol = (mat == 0) ? g_ql : (mat == 1 ? g_kl : g_vl);
                long o0 = (((long)b * H_ + h) * S_ + s) * D_ + d;
                __nv_bfloat16 h0, h1, h2, h3, l0, l1, l2, l3;
                split_bf16(c[0], h0, l0); split_bf16(c[1], h1, l1);
                split_bf16(c[2], h2, l2); split_bf16(c[3], h3, l3);
                *(__nv_bfloat162*)(oh + o0)          = __nv_bfloat162(h0, h1);
                *(__nv_bfloat162*)(ol + o0)          = __nv_bfloat162(l0, l1);
                *(__nv_bfloat162*)(oh + o0 + 8 * D_) = __nv_bfloat162(h2, h3);
                *(__nv_bfloat162*)(ol + o0 + 8 * D_) = __nv_bfloat162(l2, l3);
            }
        }
    }
}

// Output projection: BN=64 (round-11 best shape), grid (8, 32) = 256 CTAs.
__global__ void __launch_bounds__(256, 2) mma_gemm_out(float* __restrict__ C)
{
    extern __shared__ char sm[];
    uint32_t sb = smem_u32(sm);
    const int m0 = blockIdx.y << 7;
    const int nbase = blockIdx.x << 6;       // 0..448
    float acc[2][4][4];
    gemm_mainloop_t<64>(sb, m0, 3 * DM_ + nbase, acc);

    const int lane = threadIdx.x & 31, w = threadIdx.x >> 5;
    const int wM = (w & 3) * 32, wN = (w >> 2) * 32;
#pragma unroll
    for (int mt = 0; mt < 2; mt++) {
        int r0 = m0 + wM + mt * 16 + (lane >> 2);
#pragma unroll
        for (int nb = 0; nb < 2; nb++) {
#pragma unroll
            for (int nf = 0; nf < 2; nf++) {
                float* c = acc[mt][nb * 2 + nf];
                int n = nbase + wN + nb * 16 + nf * 8 + (lane & 3) * 2;
                *(float2*)(C + (long)r0 * DM_ + n)       = make_float2(c[0], c[1]);
                *(float2*)(C + (long)(r0 + 8) * DM_ + n) = make_float2(c[2], c[3]);
            }
        }
    }
}

// ---------------------------------------------------------------------------
// Flash-style tensor-core sliding-window attention, 2 CTAs/SM (unchanged,
// part of 111.3us best).
// ---------------------------------------------------------------------------
#define AT_QH   0
#define AT_QL   9216
#define AT_KH   18432
#define AT_KL   46080
#define AT_VH   18432
#define AT_VL   46080
#define AT_RED  73728
#define AT_BYTES 74752

__global__ void __launch_bounds__(256, 2) attn_k()
{
    extern __shared__ char smc[];
    uint32_t sb = smem_u32(smc);

    const int tid = threadIdx.x;
    const int lane = tid & 31, w = tid >> 5;
    const int wm = w & 3, wn = w >> 2;
    const int s0 = blockIdx.x << 6;
    const int h  = blockIdx.y;
    const int b  = blockIdx.z;
    const long base = ((long)(b * H_ + h) * S_) * D_;

#pragma unroll
    for (int it = 0; it < 2; it++) {
        int idx = tid + it * 256;
        int row = idx >> 3, dc = (idx & 7) * 8;
        uint32_t so = sb + AT_QH + row * 144 + dc * 2;
        long g = base + (long)(s0 + row) * D_ + dc;
        cpa16(so, g_qh + g);
        cpa16(so + (AT_QL - AT_QH), g_ql + g);
    }
#pragma unroll
    for (int it = 0; it < 6; it++) {
        int idx = tid + it * 256;
        int jr = idx >> 3, dc = (idx & 7) * 8;
        int kg = s0 - (W_ - 1) + jr;
        uint32_t ok = (kg >= 0) ? 16u : 0u;
        long g = base + (long)(kg >= 0 ? kg : 0) * D_ + dc;
        uint32_t sk = sb + AT_KH + jr * 144 + dc * 2;
        cpa16z(sk,         g_kh + g, ok);
        cpa16z(sk + 27648, g_kl + g, ok);
    }
    asm volatile("cp.async.commit_group;" ::: "memory");
    asm volatile("cp.async.wait_group 0;" ::: "memory");
    __syncthreads();

    float sacc[12][4];
#pragma unroll
    for (int i = 0; i < 12; i++)
#pragma unroll
        for (int e = 0; e < 4; e++) sacc[i][e] = 0.f;

    {
        const int arow = wm * 16 + (lane & 15);
        const int akoff = (lane >> 4) * 8;
        const int brL = ((lane >> 4) ? 8 : 0) + (lane & 7);
        const int bkoff = ((lane >> 3) & 1) * 8;
#pragma unroll
        for (int ks = 0; ks < 4; ks++) {
            uint32_t aq = sb + AT_QH + (arow * 72 + ks * 16 + akoff) * 2;
            uint32_t a_h[4], a_l[4];
            LDSM4(a_h, aq);
            LDSM4(a_l, aq + (AT_QL - AT_QH));
#pragma unroll
            for (int nb = 0; nb < 6; nb++) {
                int nrow = wn * 96 + nb * 16 + brL;
                uint32_t bk = sb + AT_KH + (nrow * 72 + ks * 16 + bkoff) * 2;
                uint32_t b_h[4], b_l[4];
                LDSM4(b_h, bk);
                LDSM4(b_l, bk + 27648);
                MMA16816(sacc[nb * 2 + 0], a_h, b_h[0], b_h[1]);
                MMA16816(sacc[nb * 2 + 0], a_h, b_l[0], b_l[1]);
                MMA16816(sacc[nb * 2 + 0], a_l, b_h[0], b_h[1]);
                MMA16816(sacc[nb * 2 + 1], a_h, b_h[2], b_h[3]);
                MMA16816(sacc[nb * 2 + 1], a_h, b_l[2], b_l[3]);
                MMA16816(sacc[nb * 2 + 1], a_l, b_h[2], b_h[3]);
            }
        }
    }
    __syncthreads();   // all warps done reading K; V may overwrite it

#pragma unroll
    for (int it = 0; it < 6; it++) {
        int idx = tid + it * 256;
        int jr = idx >> 3, dc = (idx & 7) * 8;
        int kg = s0 - (W_ - 1) + jr;
        uint32_t ok = (kg >= 0) ? 16u : 0u;
        long g = base + (long)(kg >= 0 ? kg : 0) * D_ + dc;
        uint32_t sv = sb + AT_VH + jr * 144 + dc * 2;
        cpa16z(sv,         g_vh + g, ok);
        cpa16z(sv + 27648, g_vl + g, ok);
    }
    asm volatile("cp.async.commit_group;" ::: "memory");

    const int i_t = wm * 16 + (lane >> 2);
    const int i_b = i_t + 8;
    const int lo_t = (i_t > (W_ - 1) - s0) ? i_t : ((W_ - 1) - s0);
    const int hi_t = i_t + (W_ - 1);
    const int lo_b = (i_b > (W_ - 1) - s0) ? i_b : ((W_ - 1) - s0);
    const int hi_b = i_b + (W_ - 1);
#pragma unroll
    for (int t = 0; t < 12; t++) {
        int j0 = wn * 96 + t * 8 + (lane & 3) * 2;
        float* c = sacc[t];
        c[0] = (j0     >= lo_t && j0     <= hi_t) ? c[0] * 0.125f : -3.0e38f;
        c[1] = (j0 + 1 >= lo_t && j0 + 1 <= hi_t) ? c[1] * 0.125f : -3.0e38f;
        c[2] = (j0     >= lo_b && j0     <= hi_b) ? c[2] * 0.125f : -3.0e38f;
        c[3] = (j0 + 1 >= lo_b && j0 + 1 <= hi_b) ? c[3] * 0.125f : -3.0e38f;
    }

    float* Red = (float*)(smc + AT_RED);
    float mt = -3.0e38f, mb = -3.0e38f;
#pragma unroll
    for (int t = 0; t < 12; t++) {
        mt = fmaxf(mt, fmaxf(sacc[t][0], sacc[t][1]));
        mb = fmaxf(mb, fmaxf(sacc[t][2], sacc[t][3]));
    }
    mt = fmaxf(mt, __shfl_xor_sync(0xffffffffu, mt, 1));
    mt = fmaxf(mt, __shfl_xor_sync(0xffffffffu, mt, 2));
    mb = fmaxf(mb, __shfl_xor_sync(0xffffffffu, mb, 1));
    mb = fmaxf(mb, __shfl_xor_sync(0xffffffffu, mb, 2));
    if ((lane & 3) == 0) {
        Red[wn * 64 + i_t] = mt;
        Red[wn * 64 + i_b] = mb;
    }
    __syncthreads();
    const float Mt = fmaxf(Red[i_t], Red[64 + i_t]);
    const float Mb = fmaxf(Red[i_b], Red[64 + i_b]);

    float st = 0.f, sbt = 0.f;
#pragma unroll
    for (int t = 0; t < 12; t++) {
        float* c = sacc[t];
        c[0] = __expf(c[0] - Mt);
        c[1] = __expf(c[1] - Mt);
        c[2] = __expf(c[2] - Mb);
        c[3] = __expf(c[3] - Mb);
        st  += c[0] + c[1];
        sbt += c[2] + c[3];
    }
    st  += __shfl_xor_sync(0xffffffffu, st, 1);
    st  += __shfl_xor_sync(0xffffffffu, st, 2);
    sbt += __shfl_xor_sync(0xffffffffu, sbt, 1);
    sbt += __shfl_xor_sync(0xffffffffu, sbt, 2);
    if ((lane & 3) == 0) {
        Red[128 + wn * 64 + i_t] = st;
        Red[128 + wn * 64 + i_b] = sbt;
    }
    __syncthreads();
    const float inv_t = 1.0f / (Red[128 + i_t] + Red[192 + i_t]);
    const float inv_b = 1.0f / (Red[128 + i_b] + Red[192 + i_b]);

    uint32_t pah[6][4], pal[6][4];
#pragma unroll
    for (int ks = 0; ks < 6; ks++) {
        float* c0 = sacc[2 * ks];
        float* c1 = sacc[2 * ks + 1];
        __nv_bfloat16 h00, h01, h02, h03, h10, h11, h12, h13;
        __nv_bfloat16 l00, l01, l02, l03, l10, l11, l12, l13;
        split_bf16(c0[0] * inv_t, h00, l00);
        split_bf16(c0[1] * inv_t, h01, l01);
        split_bf16(c0[2] * inv_b, h02, l02);
        split_bf16(c0[3] * inv_b, h03, l03);
        split_bf16(c1[0] * inv_t, h10, l10);
        split_bf16(c1[1] * inv_t, h11, l11);
        split_bf16(c1[2] * inv_b, h12, l12);
        split_bf16(c1[3] * inv_b, h13, l13);
        pah[ks][0] = pkbf(h00, h01); pah[ks][1] = pkbf(h02, h03);
        pah[ks][2] = pkbf(h10, h11); pah[ks][3] = pkbf(h12, h13);
        pal[ks][0] = pkbf(l00, l01); pal[ks][1] = pkbf(l02, l03);
        pal[ks][2] = pkbf(l10, l11); pal[ks][3] = pkbf(l12, l13);
    }

    asm volatile("cp.async.wait_group 0;" ::: "memory");
    __syncthreads();

    float oacc[8][4];
#pragma unroll
    for (int i = 0; i < 8; i++)
#pragma unroll
        for (int e = 0; e < 4; e++) oacc[i][e] = 0.f;

    {
        const int jrow = wn * 96 + (lane & 15);
        const int dsel = (lane >> 4) * 8;
#pragma unroll
        for (int ks = 0; ks < 6; ks++) {
#pragma unroll
            for (int db = 0; db < 4; db++) {
                uint32_t bv = sb + AT_VH + ((jrow + ks * 16) * 72 + db * 16 + dsel) * 2;
                uint32_t b_h[4], b_l[4];
                LDSM4T(b_h, bv);
                LDSM4T(b_l, bv + 27648);
                MMA16816(oacc[db * 2 + 0], pah[ks], b_h[0], b_h[1]);
                MMA16816(oacc[db * 2 + 0], pah[ks], b_l[0], b_l[1]);
                MMA16816(oacc[db * 2 + 0], pal[ks], b_h[0], b_h[1]);
                MMA16816(oacc[db * 2 + 1], pah[ks], b_h[2], b_h[3]);
                MMA16816(oacc[db * 2 + 1], pah[ks], b_l[2], b_l[3]);
                MMA16816(oacc[db * 2 + 1], pal[ks], b_h[2], b_h[3]);
            }
        }
    }
    __syncthreads();

    float* Obuf = (float*)smc + wn * (64 * 66);
#pragma unroll
    for (int t = 0; t < 8; t++) {
        int d = t * 8 + (lane & 3) * 2;
        *(float2*)(Obuf + i_t * 66 + d) = make_float2(oacc[t][0], oacc[t][1]);
        *(float2*)(Obuf + i_b * 66 + d) = make_float2(oacc[t][2], oacc[t][3]);
    }
    __syncthreads();

    float* Ob0 = (float*)smc;
    float* Ob1 = (float*)smc + 64 * 66;
#pragma unroll
    for (int it = 0; it < 2; it++) {
        int idx = tid + it * 256;
        int row = idx >> 3, dg = (idx & 7) * 8;
        __nv_bfloat16 hh[8], ll[8];
#pragma unroll
        for (int e = 0; e < 8; e++) {
            float v = Ob0[row * 66 + dg + e] + Ob1[row * 66 + dg + e];
            split_bf16(v, hh[e], ll[e]);
        }
        long gidx = ((long)(b * S_ + s0 + row)) * DM_ + h * D_ + dg;
        *(uint4*)(g_ah + gidx) = *(uint4*)hh;
        *(uint4*)(g_al + gidx) = *(uint4*)ll;
    }
}

// ---------------------------------------------------------------------------
extern "C" void kernel_launch(void* const* d_in, const int* in_sizes, int n_in,
                              void* d_out, int out_size)
{
    const float* x  = (const float*)d_in[0];
    const float* Wq = (const float*)d_in[1];
    const float* Wk = (const float*)d_in[2];
    const float* Wv = (const float*)d_in[3];
    const float* Wo = (const float*)d_in[4];
    float* out = (float*)d_out;

    const int qkv_smem = 3 * (16384 + 128 * 128);   // 96KB
    const int out_smem = 3 * (16384 + 64 * 128);    // 72KB
    cudaFuncSetAttribute(mma_gemm_qkv, cudaFuncAttributeMaxDynamicSharedMemorySize, qkv_smem);
    cudaFuncSetAttribute(mma_gemm_out, cudaFuncAttributeMaxDynamicSharedMemorySize, out_smem);
    cudaFuncSetAttribute(attn_k, cudaFuncAttributeMaxDynamicSharedMemorySize, AT_BYTES);

    conv_k<<<3072, 256>>>(x, Wq, Wk, Wv, Wo);
    mma_gemm_qkv<<<dim3(12, 32), 256, qkv_smem>>>();
    attn_k<<<dim3(S_ / 64, H_, B_), 256, AT_BYTES>>>();
    mma_gemm_out<<<dim3(8, 32), 256, out_smem>>>(out);
}

// round 16
// speedup vs baseline: 1.4649x; 1.4649x over previous
#include <cuda_runtime.h>
#include <cuda_bf16.h>
#include <math.h>
#include <stdint.h>

#define B_  2
#define S_  2048
#define H_  8
#define D_  64
#define DM_ 512
#define W_  128

// ---------------- scratch (device globals; no allocation) ------------------
__device__ __nv_bfloat16 g_qh[B_*H_*S_*D_];
__device__ __nv_bfloat16 g_ql[B_*H_*S_*D_];
__device__ __nv_bfloat16 g_kh[B_*H_*S_*D_];
__device__ __nv_bfloat16 g_kl[B_*H_*S_*D_];
__device__ __nv_bfloat16 g_vh[B_*H_*S_*D_];
__device__ __nv_bfloat16 g_vl[B_*H_*S_*D_];
__device__ __nv_bfloat16 g_ah[B_*S_*DM_];
__device__ __nv_bfloat16 g_al[B_*S_*DM_];
__device__ __nv_bfloat16 g_wh[4*DM_*DM_];     // W^T hi: rows 0..1535 Wq,Wk,Wv; 1536.. Wo
__device__ __nv_bfloat16 g_wl[4*DM_*DM_];     // W^T lo
// split-K partial sums for the output projection
__device__ float g_p0[B_*S_*DM_];
__device__ float g_p1[B_*S_*DM_];

__device__ __forceinline__ uint32_t smem_u32(const void* p) {
    uint32_t a;
    asm("{ .reg .u64 t; cvta.to.shared.u64 t, %1; cvt.u32.u64 %0, t; }" : "=r"(a) : "l"(p));
    return a;
}

// ---------------- mma.sync building blocks (plain sm_103 PTX) --------------
#define LDSM4(r, addr) \
    asm volatile("ldmatrix.sync.aligned.m8n8.x4.shared.b16 {%0,%1,%2,%3}, [%4];" \
        : "=r"((r)[0]), "=r"((r)[1]), "=r"((r)[2]), "=r"((r)[3]) : "r"(addr))

#define LDSM4T(r, addr) \
    asm volatile("ldmatrix.sync.aligned.m8n8.x4.trans.shared.b16 {%0,%1,%2,%3}, [%4];" \
        : "=r"((r)[0]), "=r"((r)[1]), "=r"((r)[2]), "=r"((r)[3]) : "r"(addr))

#define MMA16816(c, a, b0, b1) \
    asm volatile("mma.sync.aligned.m16n8k16.row.col.f32.bf16.bf16.f32 " \
        "{%0,%1,%2,%3}, {%4,%5,%6,%7}, {%8,%9}, {%0,%1,%2,%3};" \
        : "+f"((c)[0]), "+f"((c)[1]), "+f"((c)[2]), "+f"((c)[3]) \
        : "r"((a)[0]), "r"((a)[1]), "r"((a)[2]), "r"((a)[3]), "r"(b0), "r"(b1))

__device__ __forceinline__ void cpa16(uint32_t s, const __nv_bfloat16* g) {
    asm volatile("cp.async.ca.shared.global [%0], [%1], 16;" :: "r"(s), "l"(g));
}
__device__ __forceinline__ void cpa16z(uint32_t s, const __nv_bfloat16* g, uint32_t sz) {
    asm volatile("cp.async.ca.shared.global [%0], [%1], 16, %2;" :: "r"(s), "l"(g), "r"(sz));
}

__device__ __forceinline__ void split_bf16(float x, __nv_bfloat16& h, __nv_bfloat16& l) {
    h = __float2bfloat16(x);
    l = __float2bfloat16(x - __bfloat162float(h));
}
__device__ __forceinline__ uint32_t pkbf(__nv_bfloat16 x, __nv_bfloat16 y) {
    __nv_bfloat162 t(x, y);
    return *(uint32_t*)&t;
}

// ---------------------------------------------------------------------------
// Merged conversion kernel: blocks [0,2048) split X; [2048,3072) split+T W.
// ---------------------------------------------------------------------------
__global__ void __launch_bounds__(256) conv_k(const float* __restrict__ X,
                                              const float* __restrict__ Wq,
                                              const float* __restrict__ Wk,
                                              const float* __restrict__ Wv,
                                              const float* __restrict__ Wo)
{
    __shared__ float t[32][33];
    if (blockIdx.x < 2048) {
        int i = (blockIdx.x * 256 + threadIdx.x) * 4;
        float4 v = *(const float4*)(X + i);
        __nv_bfloat16 h0, h1, h2, h3, l0, l1, l2, l3;
        split_bf16(v.x, h0, l0); split_bf16(v.y, h1, l1);
        split_bf16(v.z, h2, l2); split_bf16(v.w, h3, l3);
        *(__nv_bfloat162*)(g_ah + i)     = __nv_bfloat162(h0, h1);
        *(__nv_bfloat162*)(g_ah + i + 2) = __nv_bfloat162(h2, h3);
        *(__nv_bfloat162*)(g_al + i)     = __nv_bfloat162(l0, l1);
        *(__nv_bfloat162*)(g_al + i + 2) = __nv_bfloat162(l2, l3);
        return;
    }
    int wi = blockIdx.x - 2048;
    int z  = wi >> 8;
    int bn = (wi & 15) * 32;
    int bk = ((wi >> 4) & 15) * 32;
    const float* Wsrc = (z == 0) ? Wq : (z == 1 ? Wk : (z == 2 ? Wv : Wo));
    int lx = threadIdx.x & 31, ly = threadIdx.x >> 5;
#pragma unroll
    for (int i = 0; i < 32; i += 8)
        t[ly + i][lx] = Wsrc[(bk + ly + i) * DM_ + bn + lx];
    __syncthreads();
    int rowbase = z * DM_;
#pragma unroll
    for (int i = 0; i < 32; i += 8) {
        int r = ly + i;
        float x = t[lx][r];
        __nv_bfloat16 h, l;
        split_bf16(x, h, l);
        long idx = (long)(rowbase + bn + r) * DM_ + bk + lx;
        g_wh[idx] = h;
        g_wl[idx] = l;
    }
}

// ---------------------------------------------------------------------------
// mma.sync split-bf16 GEMM (exact round-9 core: BM=128, BN=128, BK=32,
// 256 threads, warp tile 32x64, 3-stage cp.async, swizzled 64B rows).
// Generalized with (kbase, nchunks) for split-K; qkv uses (0,16).
// ---------------------------------------------------------------------------
#define GSTAGE 32768
#define GSM_BYTES (3 * GSTAGE)

__device__ __forceinline__ void stage(uint32_t sb, int st, int m0, int nbase, int k0)
{
    const int tid = threadIdx.x;
#pragma unroll
    for (int i = 0; i < 2; i++) {
        int u = tid + (i << 8);
        int r = u >> 2, seg = u & 3;
        int sw = ((seg + (r >> 1)) & 3) * 16;
        uint32_t so = sb + st * GSTAGE + r * 64 + sw;
        long ga = (long)(m0 + r) * DM_ + k0 + seg * 8;
        long gb = (long)(nbase + r) * DM_ + k0 + seg * 8;
        cpa16(so,         g_ah + ga);
        cpa16(so + 8192,  g_al + ga);
        cpa16(so + 16384, g_wh + gb);
        cpa16(so + 24576, g_wl + gb);
    }
    asm volatile("cp.async.commit_group;" ::: "memory");
}

__device__ __forceinline__ void compute_chunk(uint32_t sb, int st, float acc[2][8][4])
{
    const int lane = threadIdx.x & 31, w = threadIdx.x >> 5;
    const int wM = (w & 3) * 32, wN = (w >> 2) * 64;
    uint32_t base = sb + st * GSTAGE;
    const int arow_ = wM + (lane & 15);
    const int ach = lane >> 4;                 // 0/1
    const int brow_ = wN + ((lane >> 4) ? 8 : 0) + (lane & 7);
    const int bch = (lane >> 3) & 1;

#pragma unroll
    for (int kk = 0; kk < 2; kk++) {
        uint32_t a_hi[2][4], a_lo[2][4];
#pragma unroll
        for (int mt = 0; mt < 2; mt++) {
            int row = arow_ + mt * 16;
            int ch = ((kk * 2 + ach + (row >> 1)) & 3) * 16;
            uint32_t ad = base + row * 64 + ch;
            LDSM4(a_hi[mt], ad);
            LDSM4(a_lo[mt], ad + 8192);
        }
#pragma unroll
        for (int nb = 0; nb < 4; nb++) {
            int row = brow_ + nb * 16;
            int ch = ((kk * 2 + bch + (row >> 1)) & 3) * 16;
            uint32_t bd = base + 16384 + row * 64 + ch;
            uint32_t bh[4], bl[4];
            LDSM4(bh, bd);
            LDSM4(bl, bd + 8192);
#pragma unroll
            for (int mt = 0; mt < 2; mt++) {
                MMA16816(acc[mt][nb * 2 + 0], a_hi[mt], bh[0], bh[1]);
                MMA16816(acc[mt][nb * 2 + 0], a_hi[mt], bl[0], bl[1]);
                MMA16816(acc[mt][nb * 2 + 0], a_lo[mt], bh[0], bh[1]);
                MMA16816(acc[mt][nb * 2 + 1], a_hi[mt], bh[2], bh[3]);
                MMA16816(acc[mt][nb * 2 + 1], a_hi[mt], bl[2], bl[3]);
                MMA16816(acc[mt][nb * 2 + 1], a_lo[mt], bh[2], bh[3]);
            }
        }
    }
}

__device__ __forceinline__ void gemm_mainloop(uint32_t sb, int m0, int nbase,
                                              float acc[2][8][4],
                                              int kbase, int nch)
{
#pragma unroll
    for (int mt = 0; mt < 2; mt++)
#pragma unroll
        for (int nf = 0; nf < 8; nf++)
#pragma unroll
            for (int e = 0; e < 4; e++) acc[mt][nf][e] = 0.f;

    stage(sb, 0, m0, nbase, kbase);
    stage(sb, 1, m0, nbase, kbase + 32);
    for (int c = 0; c < nch; c++) {
        if (c < nch - 1) asm volatile("cp.async.wait_group 1;" ::: "memory");
        else             asm volatile("cp.async.wait_group 0;" ::: "memory");
        __syncthreads();
        compute_chunk(sb, c % 3, acc);
        if (c < nch - 2) stage(sb, (c + 2) % 3, m0, nbase, kbase + (c + 2) * 32);
    }
}

__global__ void __launch_bounds__(256, 2) mma_gemm_qkv()
{
    extern __shared__ char sm[];
    uint32_t sb = smem_u32(sm);
    const int m0 = blockIdx.y << 7;
    const int nbase = blockIdx.x << 7;
    float acc[2][8][4];
    gemm_mainloop(sb, m0, nbase, acc, 0, 16);

    const int lane = threadIdx.x & 31, w = threadIdx.x >> 5;
    const int wM = (w & 3) * 32, wN = (w >> 2) * 64;
#pragma unroll
    for (int mt = 0; mt < 2; mt++) {
        int r0 = m0 + wM + mt * 16 + (lane >> 2);
        int b = r0 >> 11, s = r0 & (S_ - 1);
#pragma unroll
        for (int nb = 0; nb < 4; nb++) {
#pragma unroll
            for (int nf = 0; nf < 2; nf++) {
                float* c = acc[mt][nb * 2 + nf];
                int n = nbase + wN + nb * 16 + nf * 8 + (lane & 3) * 2;
                int mat = n >> 9, cc = n & 511;
                int h = cc >> 6, d = cc & 63;
                __nv_bfloat16* oh = (mat == 0) ? g_qh : (mat == 1 ? g_kh : g_vh);
                __nv_bfloat16* ol = (mat == 0) ? g_ql : (mat == 1 ? g_kl : g_vl);
                long o0 = (((long)b * H_ + h) * S_ + s) * D_ + d;
                __nv_bfloat16 h0, h1, h2, h3, l0, l1, l2, l3;
                split_bf16(c[0], h0, l0); split_bf16(c[1], h1, l1);
                split_bf16(c[2], h2, l2); split_bf16(c[3], h3, l3);
                *(__nv_bfloat162*)(oh + o0)          = __nv_bfloat162(h0, h1);
                *(__nv_bfloat162*)(ol + o0)          = __nv_bfloat162(l0, l1);
                *(__nv_bfloat162*)(oh + o0 + 8 * D_) = __nv_bfloat162(h2, h3);
                *(__nv_bfloat162*)(ol + o0 + 8 * D_) = __nv_bfloat162(l2, l3);
            }
        }
    }
}

// Output projection with split-K2: blockIdx.z selects K half; partials to
// g_p0/g_p1; tiny add kernel finishes.
__global__ void __launch_bounds__(256, 2) mma_gemm_out()
{
    extern __shared__ char sm[];
    uint32_t sb = smem_u32(sm);
    const int m0 = blockIdx.y << 7;
    const int nbase = blockIdx.x << 7;
    float* P = (blockIdx.z == 0) ? g_p0 : g_p1;
    float acc[2][8][4];
    gemm_mainloop(sb, m0, 3 * DM_ + nbase, acc, blockIdx.z * 256, 8);

    const int lane = threadIdx.x & 31, w = threadIdx.x >> 5;
    const int wM = (w & 3) * 32, wN = (w >> 2) * 64;
#pragma unroll
    for (int mt = 0; mt < 2; mt++) {
        int r0 = m0 + wM + mt * 16 + (lane >> 2);
#pragma unroll
        for (int nb = 0; nb < 4; nb++) {
#pragma unroll
            for (int nf = 0; nf < 2; nf++) {
                float* c = acc[mt][nb * 2 + nf];
                int n = nbase + wN + nb * 16 + nf * 8 + (lane & 3) * 2;
                *(float2*)(P + (long)r0 * DM_ + n)       = make_float2(c[0], c[1]);
                *(float2*)(P + (long)(r0 + 8) * DM_ + n) = make_float2(c[2], c[3]);
            }
        }
    }
}

__global__ void __launch_bounds__(256) addc_k(float* __restrict__ C)
{
    int i = (blockIdx.x * 256 + threadIdx.x) * 4;
    float4 a = *(const float4*)(g_p0 + i);
    float4 b = *(const float4*)(g_p1 + i);
    *(float4*)(C + i) = make_float4(a.x + b.x, a.y + b.y, a.z + b.z, a.w + b.w);
}

// ---------------------------------------------------------------------------
// Flash-style tensor-core sliding-window attention, 2 CTAs/SM (exact R9).
// ---------------------------------------------------------------------------
#define AT_QH   0
#define AT_QL   9216
#define AT_KH   18432
#define AT_KL   46080
#define AT_VH   18432
#define AT_VL   46080
#define AT_RED  73728
#define AT_BYTES 74752

__global__ void __launch_bounds__(256, 2) attn_k()
{
    extern __shared__ char smc[];
    uint32_t sb = smem_u32(smc);

    const int tid = threadIdx.x;
    const int lane = tid & 31, w = tid >> 5;
    const int wm = w & 3, wn = w >> 2;
    const int s0 = blockIdx.x << 6;
    const int h  = blockIdx.y;
    const int b  = blockIdx.z;
    const long base = ((long)(b * H_ + h) * S_) * D_;

#pragma unroll
    for (int it = 0; it < 2; it++) {
        int idx = tid + it * 256;
        int row = idx >> 3, dc = (idx & 7) * 8;
        uint32_t so = sb + AT_QH + row * 144 + dc * 2;
        long g = base + (long)(s0 + row) * D_ + dc;
        cpa16(so, g_qh + g);
        cpa16(so + (AT_QL - AT_QH), g_ql + g);
    }
#pragma unroll
    for (int it = 0; it < 6; it++) {
        int idx = tid + it * 256;
        int jr = idx >> 3, dc = (idx & 7) * 8;
        int kg = s0 - (W_ - 1) + jr;
        uint32_t ok = (kg >= 0) ? 16u : 0u;
        long g = base + (long)(kg >= 0 ? kg : 0) * D_ + dc;
        uint32_t sk = sb + AT_KH + jr * 144 + dc * 2;
        cpa16z(sk,         g_kh + g, ok);
        cpa16z(sk + 27648, g_kl + g, ok);
    }
    asm volatile("cp.async.commit_group;" ::: "memory");
    asm volatile("cp.async.wait_group 0;" ::: "memory");
    __syncthreads();

    float sacc[12][4];
#pragma unroll
    for (int i = 0; i < 12; i++)
#pragma unroll
        for (int e = 0; e < 4; e++) sacc[i][e] = 0.f;

    {
        const int arow = wm * 16 + (lane & 15);
        const int akoff = (lane >> 4) * 8;
        const int brL = ((lane >> 4) ? 8 : 0) + (lane & 7);
        const int bkoff = ((lane >> 3) & 1) * 8;
#pragma unroll
        for (int ks = 0; ks < 4; ks++) {
            uint32_t aq = sb + AT_QH + (arow * 72 + ks * 16 + akoff) * 2;
            uint32_t a_h[4], a_l[4];
            LDSM4(a_h, aq);
            LDSM4(a_l, aq + (AT_QL - AT_QH));
#pragma unroll
            for (int nb = 0; nb < 6; nb++) {
                int nrow = wn * 96 + nb * 16 + brL;
                uint32_t bk = sb + AT_KH + (nrow * 72 + ks * 16 + bkoff) * 2;
                uint32_t b_h[4], b_l[4];
                LDSM4(b_h, bk);
                LDSM4(b_l, bk + 27648);
                MMA16816(sacc[nb * 2 + 0], a_h, b_h[0], b_h[1]);
                MMA16816(sacc[nb * 2 + 0], a_h, b_l[0], b_l[1]);
                MMA16816(sacc[nb * 2 + 0], a_l, b_h[0], b_h[1]);
                MMA16816(sacc[nb * 2 + 1], a_h, b_h[2], b_h[3]);
                MMA16816(sacc[nb * 2 + 1], a_h, b_l[2], b_l[3]);
                MMA16816(sacc[nb * 2 + 1], a_l, b_h[2], b_h[3]);
            }
        }
    }
    __syncthreads();   // all warps done reading K; V may overwrite it

#pragma unroll
    for (int it = 0; it < 6; it++) {
        int idx = tid + it * 256;
        int jr = idx >> 3, dc = (idx & 7) * 8;
        int kg = s0 - (W_ - 1) + jr;
        uint32_t ok = (kg >= 0) ? 16u : 0u;
        long g = base + (long)(kg >= 0 ? kg : 0) * D_ + dc;
        uint32_t sv = sb + AT_VH + jr * 144 + dc * 2;
        cpa16z(sv,         g_vh + g, ok);
        cpa16z(sv + 27648, g_vl + g, ok);
    }
    asm volatile("cp.async.commit_group;" ::: "memory");

    const int i_t = wm * 16 + (lane >> 2);
    const int i_b = i_t + 8;
    const int lo_t = (i_t > (W_ - 1) - s0) ? i_t : ((W_ - 1) - s0);
    const int hi_t = i_t + (W_ - 1);
    const int lo_b = (i_b > (W_ - 1) - s0) ? i_b : ((W_ - 1) - s0);
    const int hi_b = i_b + (W_ - 1);
#pragma unroll
    for (int t = 0; t < 12; t++) {
        int j0 = wn * 96 + t * 8 + (lane & 3) * 2;
        float* c = sacc[t];
        c[0] = (j0     >= lo_t && j0     <= hi_t) ? c[0] * 0.125f : -3.0e38f;
        c[1] = (j0 + 1 >= lo_t && j0 + 1 <= hi_t) ? c[1] * 0.125f : -3.0e38f;
        c[2] = (j0     >= lo_b && j0     <= hi_b) ? c[2] * 0.125f : -3.0e38f;
        c[3] = (j0 + 1 >= lo_b && j0 + 1 <= hi_b) ? c[3] * 0.125f : -3.0e38f;
    }

    float* Red = (float*)(smc + AT_RED);
    float mt = -3.0e38f, mb = -3.0e38f;
#pragma unroll
    for (int t = 0; t < 12; t++) {
        mt = fmaxf(mt, fmaxf(sacc[t][0], sacc[t][1]));
        mb = fmaxf(mb, fmaxf(sacc[t][2], sacc[t][3]));
    }
    mt = fmaxf(mt, __shfl_xor_sync(0xffffffffu, mt, 1));
    mt = fmaxf(mt, __shfl_xor_sync(0xffffffffu, mt, 2));
    mb = fmaxf(mb, __shfl_xor_sync(0xffffffffu, mb, 1));
    mb = fmaxf(mb, __shfl_xor_sync(0xffffffffu, mb, 2));
    if ((lane & 3) == 0) {
        Red[wn * 64 + i_t] = mt;
        Red[wn * 64 + i_b] = mb;
    }
    __syncthreads();
    const float Mt = fmaxf(Red[i_t], Red[64 + i_t]);
    const float Mb = fmaxf(Red[i_b], Red[64 + i_b]);

    float st = 0.f, sbt = 0.f;
#pragma unroll
    for (int t = 0; t < 12; t++) {
        float* c = sacc[t];
        c[0] = __expf(c[0] - Mt);
        c[1] = __expf(c[1] - Mt);
        c[2] = __expf(c[2] - Mb);
        c[3] = __expf(c[3] - Mb);
        st  += c[0] + c[1];
        sbt += c[2] + c[3];
    }
    st  += __shfl_xor_sync(0xffffffffu, st, 1);
    st  += __shfl_xor_sync(0xffffffffu, st, 2);
    sbt += __shfl_xor_sync(0xffffffffu, sbt, 1);
    sbt += __shfl_xor_sync(0xffffffffu, sbt, 2);
    if ((lane & 3) == 0) {
        Red[128 + wn * 64 + i_t] = st;
        Red[128 + wn * 64 + i_b] = sbt;
    }
    __syncthreads();
    const float inv_t = 1.0f / (Red[128 + i_t] + Red[192 + i_t]);
    const float inv_b = 1.0f / (Red[128 + i_b] + Red[192 + i_b]);

    uint32_t pah[6][4], pal[6][4];
#pragma unroll
    for (int ks = 0; ks < 6; ks++) {
        float* c0 = sacc[2 * ks];
        float* c1 = sacc[2 * ks + 1];
        __nv_bfloat16 h00, h01, h02, h03, h10, h11, h12, h13;
        __nv_bfloat16 l00, l01, l02, l03, l10, l11, l12, l13;
        split_bf16(c0[0] * inv_t, h00, l00);
        split_bf16(c0[1] * inv_t, h01, l01);
        split_bf16(c0[2] * inv_b, h02, l02);
        split_bf16(c0[3] * inv_b, h03, l03);
        split_bf16(c1[0] * inv_t, h10, l10);
        split_bf16(c1[1] * inv_t, h11, l11);
        split_bf16(c1[2] * inv_b, h12, l12);
        split_bf16(c1[3] * inv_b, h13, l13);
        pah[ks][0] = pkbf(h00, h01); pah[ks][1] = pkbf(h02, h03);
        pah[ks][2] = pkbf(h10, h11); pah[ks][3] = pkbf(h12, h13);
        pal[ks][0] = pkbf(l00, l01); pal[ks][1] = pkbf(l02, l03);
        pal[ks][2] = pkbf(l10, l11); pal[ks][3] = pkbf(l12, l13);
    }

    asm volatile("cp.async.wait_group 0;" ::: "memory");
    __syncthreads();

    float oacc[8][4];
#pragma unroll
    for (int i = 0; i < 8; i++)
#pragma unroll
        for (int e = 0; e < 4; e++) oacc[i][e] = 0.f;

    {
        const int jrow = wn * 96 + (lane & 15);
        const int dsel = (lane >> 4) * 8;
#pragma unroll
        for (int ks = 0; ks < 6; ks++) {
#pragma unroll
            for (int db = 0; db < 4; db++) {
                uint32_t bv = sb + AT_VH + ((jrow + ks * 16) * 72 + db * 16 + dsel) * 2;
                uint32_t b_h[4], b_l[4];
                LDSM4T(b_h, bv);
                LDSM4T(b_l, bv + 27648);
                MMA16816(oacc[db * 2 + 0], pah[ks], b_h[0], b_h[1]);
                MMA16816(oacc[db * 2 + 0], pah[ks], b_l[0], b_l[1]);
                MMA16816(oacc[db * 2 + 0], pal[ks], b_h[0], b_h[1]);
                MMA16816(oacc[db * 2 + 1], pah[ks], b_h[2], b_h[3]);
                MMA16816(oacc[db * 2 + 1], pah[ks], b_l[2], b_l[3]);
                MMA16816(oacc[db * 2 + 1], pal[ks], b_h[2], b_h[3]);
            }
        }
    }
    __syncthreads();

    float* Obuf = (float*)smc + wn * (64 * 66);
#pragma unroll
    for (int t = 0; t < 8; t++) {
        int d = t * 8 + (lane & 3) * 2;
        *(float2*)(Obuf + i_t * 66 + d) = make_float2(oacc[t][0], oacc[t][1]);
        *(float2*)(Obuf + i_b * 66 + d) = make_float2(oacc[t][2], oacc[t][3]);
    }
    __syncthreads();

    float* Ob0 = (float*)smc;
    float* Ob1 = (float*)smc + 64 * 66;
#pragma unroll
    for (int it = 0; it < 2; it++) {
        int idx = tid + it * 256;
        int row = idx >> 3, dg = (idx & 7) * 8;
        __nv_bfloat16 hh[8], ll[8];
#pragma unroll
        for (int e = 0; e < 8; e++) {
            float v = Ob0[row * 66 + dg + e] + Ob1[row * 66 + dg + e];
            split_bf16(v, hh[e], ll[e]);
        }
        long gidx = ((long)(b * S_ + s0 + row)) * DM_ + h * D_ + dg;
        *(uint4*)(g_ah + gidx) = *(uint4*)hh;
        *(uint4*)(g_al + gidx) = *(uint4*)ll;
    }
}

// ---------------------------------------------------------------------------
extern "C" void kernel_launch(void* const* d_in, const int* in_sizes, int n_in,
                              void* d_out, int out_size)
{
    const float* x  = (const float*)d_in[0];
    const float* Wq = (const float*)d_in[1];
    const float* Wk = (const float*)d_in[2];
    const float* Wv = (const float*)d_in[3];
    const float* Wo = (const float*)d_in[4];
    float* out = (float*)d_out;

    cudaFuncSetAttribute(mma_gemm_qkv, cudaFuncAttributeMaxDynamicSharedMemorySize, GSM_BYTES);
    cudaFuncSetAttribute(mma_gemm_out, cudaFuncAttributeMaxDynamicSharedMemorySize, GSM_BYTES);
    cudaFuncSetAttribute(attn_k, cudaFuncAttributeMaxDynamicSharedMemorySize, AT_BYTES);

    conv_k<<<3072, 256>>>(x, Wq, Wk, Wv, Wo);
    mma_gemm_qkv<<<dim3(12, 32), 256, GSM_BYTES>>>();
    attn_k<<<dim3(S_ / 64, H_, B_), 256, AT_BYTES>>>();
    mma_gemm_out<<<dim3(4, 32, 2), 256, GSM_BYTES>>>();
    addc_k<<<(B_*S_*DM_) / 1024, 256>>>(out);
}

// round 17
// speedup vs baseline: 1.5219x; 1.0390x over previous
#include <cuda_runtime.h>
#include <cuda_bf16.h>
#include <math.h>
#include <stdint.h>

#define B_  2
#define S_  2048
#define H_  8
#define D_  64
#define DM_ 512
#define W_  128

// ---------------- scratch (device globals; no allocation) ------------------
__device__ __nv_bfloat16 g_qh[B_*H_*S_*D_];
__device__ __nv_bfloat16 g_ql[B_*H_*S_*D_];
__device__ __nv_bfloat16 g_kh[B_*H_*S_*D_];
__device__ __nv_bfloat16 g_kl[B_*H_*S_*D_];
__device__ __nv_bfloat16 g_vh[B_*H_*S_*D_];
__device__ __nv_bfloat16 g_vl[B_*H_*S_*D_];
__device__ __nv_bfloat16 g_ah[B_*S_*DM_];
__device__ __nv_bfloat16 g_al[B_*S_*DM_];
__device__ __nv_bfloat16 g_wh[4*DM_*DM_];     // W^T hi: rows 0..1535 Wq,Wk,Wv; 1536.. Wo
__device__ __nv_bfloat16 g_wl[4*DM_*DM_];     // W^T lo

__device__ __forceinline__ uint32_t smem_u32(const void* p) {
    uint32_t a;
    asm("{ .reg .u64 t; cvta.to.shared.u64 t, %1; cvt.u32.u64 %0, t; }" : "=r"(a) : "l"(p));
    return a;
}

// ---------------- mma.sync building blocks (plain sm_103 PTX) --------------
#define LDSM4(r, addr) \
    asm volatile("ldmatrix.sync.aligned.m8n8.x4.shared.b16 {%0,%1,%2,%3}, [%4];" \
        : "=r"((r)[0]), "=r"((r)[1]), "=r"((r)[2]), "=r"((r)[3]) : "r"(addr))

#define LDSM4T(r, addr) \
    asm volatile("ldmatrix.sync.aligned.m8n8.x4.trans.shared.b16 {%0,%1,%2,%3}, [%4];" \
        : "=r"((r)[0]), "=r"((r)[1]), "=r"((r)[2]), "=r"((r)[3]) : "r"(addr))

#define MMA16816(c, a, b0, b1) \
    asm volatile("mma.sync.aligned.m16n8k16.row.col.f32.bf16.bf16.f32 " \
        "{%0,%1,%2,%3}, {%4,%5,%6,%7}, {%8,%9}, {%0,%1,%2,%3};" \
        : "+f"((c)[0]), "+f"((c)[1]), "+f"((c)[2]), "+f"((c)[3]) \
        : "r"((a)[0]), "r"((a)[1]), "r"((a)[2]), "r"((a)[3]), "r"(b0), "r"(b1))

__device__ __forceinline__ void cpa16(uint32_t s, const __nv_bfloat16* g) {
    asm volatile("cp.async.ca.shared.global [%0], [%1], 16;" :: "r"(s), "l"(g));
}
__device__ __forceinline__ void cpa16z(uint32_t s, const __nv_bfloat16* g, uint32_t sz) {
    asm volatile("cp.async.ca.shared.global [%0], [%1], 16, %2;" :: "r"(s), "l"(g), "r"(sz));
}

__device__ __forceinline__ void split_bf16(float x, __nv_bfloat16& h, __nv_bfloat16& l) {
    h = __float2bfloat16(x);
    l = __float2bfloat16(x - __bfloat162float(h));
}
__device__ __forceinline__ uint32_t pkbf(__nv_bfloat16 x, __nv_bfloat16 y) {
    __nv_bfloat162 t(x, y);
    return *(uint32_t*)&t;
}

// ---------------------------------------------------------------------------
// Merged conversion kernel: blocks [0,2048) split X; [2048,3072) split+T W.
// ---------------------------------------------------------------------------
__global__ void __launch_bounds__(256) conv_k(const float* __restrict__ X,
                                              const float* __restrict__ Wq,
                                              const float* __restrict__ Wk,
                                              const float* __restrict__ Wv,
                                              const float* __restrict__ Wo)
{
    __shared__ float t[32][33];
    if (blockIdx.x < 2048) {
        int i = (blockIdx.x * 256 + threadIdx.x) * 4;
        float4 v = *(const float4*)(X + i);
        __nv_bfloat16 h0, h1, h2, h3, l0, l1, l2, l3;
        split_bf16(v.x, h0, l0); split_bf16(v.y, h1, l1);
        split_bf16(v.z, h2, l2); split_bf16(v.w, h3, l3);
        *(__nv_bfloat162*)(g_ah + i)     = __nv_bfloat162(h0, h1);
        *(__nv_bfloat162*)(g_ah + i + 2) = __nv_bfloat162(h2, h3);
        *(__nv_bfloat162*)(g_al + i)     = __nv_bfloat162(l0, l1);
        *(__nv_bfloat162*)(g_al + i + 2) = __nv_bfloat162(l2, l3);
        return;
    }
    int wi = blockIdx.x - 2048;
    int z  = wi >> 8;
    int bn = (wi & 15) * 32;
    int bk = ((wi >> 4) & 15) * 32;
    const float* Wsrc = (z == 0) ? Wq : (z == 1 ? Wk : (z == 2 ? Wv : Wo));
    int lx = threadIdx.x & 31, ly = threadIdx.x >> 5;
#pragma unroll
    for (int i = 0; i < 32; i += 8)
        t[ly + i][lx] = Wsrc[(bk + ly + i) * DM_ + bn + lx];
    __syncthreads();
    int rowbase = z * DM_;
#pragma unroll
    for (int i = 0; i < 32; i += 8) {
        int r = ly + i;
        float x = t[lx][r];
        __nv_bfloat16 h, l;
        split_bf16(x, h, l);
        long idx = (long)(rowbase + bn + r) * DM_ + bk + lx;
        g_wh[idx] = h;
        g_wl[idx] = l;
    }
}

// ---------------------------------------------------------------------------
// mma.sync split-bf16 GEMM (round-9 core: BM=128, BN=128, BK=32, 256 thr,
// warp tile 32x64, 3-stage cp.async, swizzled 64B rows).
// MMA issue INTERLEAVED across accumulators (distance 4 between same-acc).
// ---------------------------------------------------------------------------
#define GSTAGE 32768
#define GSM_BYTES (3 * GSTAGE)

__device__ __forceinline__ void stage(uint32_t sb, int st, int m0, int nbase, int k0)
{
    const int tid = threadIdx.x;
#pragma unroll
    for (int i = 0; i < 2; i++) {
        int u = tid + (i << 8);
        int r = u >> 2, seg = u & 3;
        int sw = ((seg + (r >> 1)) & 3) * 16;
        uint32_t so = sb + st * GSTAGE + r * 64 + sw;
        long ga = (long)(m0 + r) * DM_ + k0 + seg * 8;
        long gb = (long)(nbase + r) * DM_ + k0 + seg * 8;
        cpa16(so,         g_ah + ga);
        cpa16(so + 8192,  g_al + ga);
        cpa16(so + 16384, g_wh + gb);
        cpa16(so + 24576, g_wl + gb);
    }
    asm volatile("cp.async.commit_group;" ::: "memory");
}

__device__ __forceinline__ void compute_chunk(uint32_t sb, int st, float acc[2][8][4])
{
    const int lane = threadIdx.x & 31, w = threadIdx.x >> 5;
    const int wM = (w & 3) * 32, wN = (w >> 2) * 64;
    uint32_t base = sb + st * GSTAGE;
    const int arow_ = wM + (lane & 15);
    const int ach = lane >> 4;                 // 0/1
    const int brow_ = wN + ((lane >> 4) ? 8 : 0) + (lane & 7);
    const int bch = (lane >> 3) & 1;

#pragma unroll
    for (int kk = 0; kk < 2; kk++) {
        uint32_t a_hi[2][4], a_lo[2][4];
#pragma unroll
        for (int mt = 0; mt < 2; mt++) {
            int row = arow_ + mt * 16;
            int ch = ((kk * 2 + ach + (row >> 1)) & 3) * 16;
            uint32_t ad = base + row * 64 + ch;
            LDSM4(a_hi[mt], ad);
            LDSM4(a_lo[mt], ad + 8192);
        }
#pragma unroll
        for (int nb = 0; nb < 4; nb++) {
            int row = brow_ + nb * 16;
            int ch = ((kk * 2 + bch + (row >> 1)) & 3) * 16;
            uint32_t bd = base + 16384 + row * 64 + ch;
            uint32_t bh[4], bl[4];
            LDSM4(bh, bd);
            LDSM4(bl, bd + 8192);
            // product-major issue: same-acc MMAs are 4 apart; per-acc order
            // stays hh -> hl -> lh (numerics identical to the R9 kernel).
            MMA16816(acc[0][nb * 2 + 0], a_hi[0], bh[0], bh[1]);
            MMA16816(acc[1][nb * 2 + 0], a_hi[1], bh[0], bh[1]);
            MMA16816(acc[0][nb * 2 + 1], a_hi[0], bh[2], bh[3]);
            MMA16816(acc[1][nb * 2 + 1], a_hi[1], bh[2], bh[3]);
            MMA16816(acc[0][nb * 2 + 0], a_hi[0], bl[0], bl[1]);
            MMA16816(acc[1][nb * 2 + 0], a_hi[1], bl[0], bl[1]);
            MMA16816(acc[0][nb * 2 + 1], a_hi[0], bl[2], bl[3]);
            MMA16816(acc[1][nb * 2 + 1], a_hi[1], bl[2], bl[3]);
            MMA16816(acc[0][nb * 2 + 0], a_lo[0], bh[0], bh[1]);
            MMA16816(acc[1][nb * 2 + 0], a_lo[1], bh[0], bh[1]);
            MMA16816(acc[0][nb * 2 + 1], a_lo[0], bh[2], bh[3]);
            MMA16816(acc[1][nb * 2 + 1], a_lo[1], bh[2], bh[3]);
        }
    }
}

__device__ __forceinline__ void gemm_mainloop(uint32_t sb, int m0, int nbase,
                                              float acc[2][8][4])
{
#pragma unroll
    for (int mt = 0; mt < 2; mt++)
#pragma unroll
        for (int nf = 0; nf < 8; nf++)
#pragma unroll
            for (int e = 0; e < 4; e++) acc[mt][nf][e] = 0.f;

    stage(sb, 0, m0, nbase, 0);
    stage(sb, 1, m0, nbase, 32);
    for (int c = 0; c < 16; c++) {
        if (c < 15) asm volatile("cp.async.wait_group 1;" ::: "memory");
        else        asm volatile("cp.async.wait_group 0;" ::: "memory");
        __syncthreads();
        compute_chunk(sb, c % 3, acc);
        if (c < 14) stage(sb, (c + 2) % 3, m0, nbase, (c + 2) * 32);
    }
}

__global__ void __launch_bounds__(256, 2) mma_gemm_qkv()
{
    extern __shared__ char sm[];
    uint32_t sb = smem_u32(sm);
    const int m0 = blockIdx.y << 7;
    const int nbase = blockIdx.x << 7;
    float acc[2][8][4];
    gemm_mainloop(sb, m0, nbase, acc);

    const int lane = threadIdx.x & 31, w = threadIdx.x >> 5;
    const int wM = (w & 3) * 32, wN = (w >> 2) * 64;
#pragma unroll
    for (int mt = 0; mt < 2; mt++) {
        int r0 = m0 + wM + mt * 16 + (lane >> 2);
        int b = r0 >> 11, s = r0 & (S_ - 1);
#pragma unroll
        for (int nb = 0; nb < 4; nb++) {
#pragma unroll
            for (int nf = 0; nf < 2; nf++) {
                float* c = acc[mt][nb * 2 + nf];
                int n = nbase + wN + nb * 16 + nf * 8 + (lane & 3) * 2;
                int mat = n >> 9, cc = n & 511;
                int h = cc >> 6, d = cc & 63;
                __nv_bfloat16* oh = (mat == 0) ? g_qh : (mat == 1 ? g_kh : g_vh);
                __nv_bfloat16* ol = (mat == 0) ? g_ql : (mat == 1 ? g_kl : g_vl);
                long o0 = (((long)b * H_ + h) * S_ + s) * D_ + d;
                __nv_bfloat16 h0, h1, h2, h3, l0, l1, l2, l3;
                split_bf16(c[0], h0, l0); split_bf16(c[1], h1, l1);
                split_bf16(c[2], h2, l2); split_bf16(c[3], h3, l3);
                *(__nv_bfloat162*)(oh + o0)          = __nv_bfloat162(h0, h1);
                *(__nv_bfloat162*)(ol + o0)          = __nv_bfloat162(l0, l1);
                *(__nv_bfloat162*)(oh + o0 + 8 * D_) = __nv_bfloat162(h2, h3);
                *(__nv_bfloat162*)(ol + o0 + 8 * D_) = __nv_bfloat162(l2, l3);
            }
        }
    }
}

__global__ void __launch_bounds__(256, 2) mma_gemm_out(float* __restrict__ C)
{
    extern __shared__ char sm[];
    uint32_t sb = smem_u32(sm);
    const int m0 = blockIdx.y << 7;
    const int nbase = blockIdx.x << 7;
    float acc[2][8][4];
    gemm_mainloop(sb, m0, 3 * DM_ + nbase, acc);

    const int lane = threadIdx.x & 31, w = threadIdx.x >> 5;
    const int wM = (w & 3) * 32, wN = (w >> 2) * 64;
#pragma unroll
    for (int mt = 0; mt < 2; mt++) {
        int r0 = m0 + wM + mt * 16 + (lane >> 2);
#pragma unroll
        for (int nb = 0; nb < 4; nb++) {
#pragma unroll
            for (int nf = 0; nf < 2; nf++) {
                float* c = acc[mt][nb * 2 + nf];
                int n = nbase + wN + nb * 16 + nf * 8 + (lane & 3) * 2;
                *(float2*)(C + (long)r0 * DM_ + n)       = make_float2(c[0], c[1]);
                *(float2*)(C + (long)(r0 + 8) * DM_ + n) = make_float2(c[2], c[3]);
            }
        }
    }
}

// ---------------------------------------------------------------------------
// Flash-style tensor-core sliding-window attention, 2 CTAs/SM (R9 structure,
// MMA issue interleaved across the 2 accumulators per tile pair).
// ---------------------------------------------------------------------------
#define AT_QH   0
#define AT_QL   9216
#define AT_KH   18432
#define AT_KL   46080
#define AT_VH   18432
#define AT_VL   46080
#define AT_RED  73728
#define AT_BYTES 74752

__global__ void __launch_bounds__(256, 2) attn_k()
{
    extern __shared__ char smc[];
    uint32_t sb = smem_u32(smc);

    const int tid = threadIdx.x;
    const int lane = tid & 31, w = tid >> 5;
    const int wm = w & 3, wn = w >> 2;
    const int s0 = blockIdx.x << 6;
    const int h  = blockIdx.y;
    const int b  = blockIdx.z;
    const long base = ((long)(b * H_ + h) * S_) * D_;

#pragma unroll
    for (int it = 0; it < 2; it++) {
        int idx = tid + it * 256;
        int row = idx >> 3, dc = (idx & 7) * 8;
        uint32_t so = sb + AT_QH + row * 144 + dc * 2;
        long g = base + (long)(s0 + row) * D_ + dc;
        cpa16(so, g_qh + g);
        cpa16(so + (AT_QL - AT_QH), g_ql + g);
    }
#pragma unroll
    for (int it = 0; it < 6; it++) {
        int idx = tid + it * 256;
        int jr = idx >> 3, dc = (idx & 7) * 8;
        int kg = s0 - (W_ - 1) + jr;
        uint32_t ok = (kg >= 0) ? 16u : 0u;
        long g = base + (long)(kg >= 0 ? kg : 0) * D_ + dc;
        uint32_t sk = sb + AT_KH + jr * 144 + dc * 2;
        cpa16z(sk,         g_kh + g, ok);
        cpa16z(sk + 27648, g_kl + g, ok);
    }
    asm volatile("cp.async.commit_group;" ::: "memory");
    asm volatile("cp.async.wait_group 0;" ::: "memory");
    __syncthreads();

    float sacc[12][4];
#pragma unroll
    for (int i = 0; i < 12; i++)
#pragma unroll
        for (int e = 0; e < 4; e++) sacc[i][e] = 0.f;

    {
        const int arow = wm * 16 + (lane & 15);
        const int akoff = (lane >> 4) * 8;
        const int brL = ((lane >> 4) ? 8 : 0) + (lane & 7);
        const int bkoff = ((lane >> 3) & 1) * 8;
#pragma unroll
        for (int ks = 0; ks < 4; ks++) {
            uint32_t aq = sb + AT_QH + (arow * 72 + ks * 16 + akoff) * 2;
            uint32_t a_h[4], a_l[4];
            LDSM4(a_h, aq);
            LDSM4(a_l, aq + (AT_QL - AT_QH));
#pragma unroll
            for (int nb = 0; nb < 6; nb++) {
                int nrow = wn * 96 + nb * 16 + brL;
                uint32_t bk = sb + AT_KH + (nrow * 72 + ks * 16 + bkoff) * 2;
                uint32_t b_h[4], b_l[4];
                LDSM4(b_h, bk);
                LDSM4(b_l, bk + 27648);
                // interleaved: same-acc distance 2, per-acc order hh->hl->lh
                MMA16816(sacc[nb * 2 + 0], a_h, b_h[0], b_h[1]);
                MMA16816(sacc[nb * 2 + 1], a_h, b_h[2], b_h[3]);
                MMA16816(sacc[nb * 2 + 0], a_h, b_l[0], b_l[1]);
                MMA16816(sacc[nb * 2 + 1], a_h, b_l[2], b_l[3]);
                MMA16816(sacc[nb * 2 + 0], a_l, b_h[0], b_h[1]);
                MMA16816(sacc[nb * 2 + 1], a_l, b_h[2], b_h[3]);
            }
        }
    }
    __syncthreads();   // all warps done reading K; V may overwrite it

#pragma unroll
    for (int it = 0; it < 6; it++) {
        int idx = tid + it * 256;
        int jr = idx >> 3, dc = (idx & 7) * 8;
        int kg = s0 - (W_ - 1) + jr;
        uint32_t ok = (kg >= 0) ? 16u : 0u;
        long g = base + (long)(kg >= 0 ? kg : 0) * D_ + dc;
        uint32_t sv = sb + AT_VH + jr * 144 + dc * 2;
        cpa16z(sv,         g_vh + g, ok);
        cpa16z(sv + 27648, g_vl + g, ok);
    }
    asm volatile("cp.async.commit_group;" ::: "memory");

    const int i_t = wm * 16 + (lane >> 2);
    const int i_b = i_t + 8;
    const int lo_t = (i_t > (W_ - 1) - s0) ? i_t : ((W_ - 1) - s0);
    const int hi_t = i_t + (W_ - 1);
    const int lo_b = (i_b > (W_ - 1) - s0) ? i_b : ((W_ - 1) - s0);
    const int hi_b = i_b + (W_ - 1);
#pragma unroll
    for (int t = 0; t < 12; t++) {
        int j0 = wn * 96 + t * 8 + (lane & 3) * 2;
        float* c = sacc[t];
        c[0] = (j0     >= lo_t && j0     <= hi_t) ? c[0] * 0.125f : -3.0e38f;
        c[1] = (j0 + 1 >= lo_t && j0 + 1 <= hi_t) ? c[1] * 0.125f : -3.0e38f;
        c[2] = (j0     >= lo_b && j0     <= hi_b) ? c[2] * 0.125f : -3.0e38f;
        c[3] = (j0 + 1 >= lo_b && j0 + 1 <= hi_b) ? c[3] * 0.125f : -3.0e38f;
    }

    float* Red = (float*)(smc + AT_RED);
    float mt = -3.0e38f, mb = -3.0e38f;
#pragma unroll
    for (int t = 0; t < 12; t++) {
        mt = fmaxf(mt, fmaxf(sacc[t][0], sacc[t][1]));
        mb = fmaxf(mb, fmaxf(sacc[t][2], sacc[t][3]));
    }
    mt = fmaxf(mt, __shfl_xor_sync(0xffffffffu, mt, 1));
    mt = fmaxf(mt, __shfl_xor_sync(0xffffffffu, mt, 2));
    mb = fmaxf(mb, __shfl_xor_sync(0xffffffffu, mb, 1));
    mb = fmaxf(mb, __shfl_xor_sync(0xffffffffu, mb, 2));
    if ((lane & 3) == 0) {
        Red[wn * 64 + i_t] = mt;
        Red[wn * 64 + i_b] = mb;
    }
    __syncthreads();
    const float Mt = fmaxf(Red[i_t], Red[64 + i_t]);
    const float Mb = fmaxf(Red[i_b], Red[64 + i_b]);

    float st = 0.f, sbt = 0.f;
#pragma unroll
    for (int t = 0; t < 12; t++) {
        float* c = sacc[t];
        c[0] = __expf(c[0] - Mt);
        c[1] = __expf(c[1] - Mt);
        c[2] = __expf(c[2] - Mb);
        c[3] = __expf(c[3] - Mb);
        st  += c[0] + c[1];
        sbt += c[2] + c[3];
    }
    st  += __shfl_xor_sync(0xffffffffu, st, 1);
    st  += __shfl_xor_sync(0xffffffffu, st, 2);
    sbt += __shfl_xor_sync(0xffffffffu, sbt, 1);
    sbt += __shfl_xor_sync(0xffffffffu, sbt, 2);
    if ((lane & 3) == 0) {
        Red[128 + wn * 64 + i_t] = st;
        Red[128 + wn * 64 + i_b] = sbt;
    }
    __syncthreads();
    const float inv_t = 1.0f / (Red[128 + i_t] + Red[192 + i_t]);
    const float inv_b = 1.0f / (Red[128 + i_b] + Red[192 + i_b]);

    uint32_t pah[6][4], pal[6][4];
#pragma unroll
    for (int ks = 0; ks < 6; ks++) {
        float* c0 = sacc[2 * ks];
        float* c1 = sacc[2 * ks + 1];
        __nv_bfloat16 h00, h01, h02, h03, h10, h11, h12, h13;
        __nv_bfloat16 l00, l01, l02, l03, l10, l11, l12, l13;
        split_bf16(c0[0] * inv_t, h00, l00);
        split_bf16(c0[1] * inv_t, h01, l01);
        split_bf16(c0[2] * inv_b, h02, l02);
        split_bf16(c0[3] * inv_b, h03, l03);
        split_bf16(c1[0] * inv_t, h10, l10);
        split_bf16(c1[1] * inv_t, h11, l11);
        split_bf16(c1[2] * inv_b, h12, l12);
        split_bf16(c1[3] * inv_b, h13, l13);
        pah[ks][0] = pkbf(h00, h01); pah[ks][1] = pkbf(h02, h03);
        pah[ks][2] = pkbf(h10, h11); pah[ks][3] = pkbf(h12, h13);
        pal[ks][0] = pkbf(l00, l01); pal[ks][1] = pkbf(l02, l03);
        pal[ks][2] = pkbf(l10, l11); pal[ks][3] = pkbf(l12, l13);
    }

    asm volatile("cp.async.wait_group 0;" ::: "memory");
    __syncthreads();

    float oacc[8][4];
#pragma unroll
    for (int i = 0; i < 8; i++)
#pragma unroll
        for (int e = 0; e < 4; e++) oacc[i][e] = 0.f;

    {
        const int jrow = wn * 96 + (lane & 15);
        const int dsel = (lane >> 4) * 8;
#pragma unroll
        for (int ks = 0; ks < 6; ks++) {
#pragma unroll
            for (int db = 0; db < 4; db++) {
                uint32_t bv = sb + AT_VH + ((jrow + ks * 16) * 72 + db * 16 + dsel) * 2;
                uint32_t b_h[4], b_l[4];
                LDSM4T(b_h, bv);
                LDSM4T(b_l, bv + 27648);
                // interleaved: same-acc distance 2, per-acc order hh->hl->lh
                MMA16816(oacc[db * 2 + 0], pah[ks], b_h[0], b_h[1]);
                MMA16816(oacc[db * 2 + 1], pah[ks], b_h[2], b_h[3]);
                MMA16816(oacc[db * 2 + 0], pah[ks], b_l[0], b_l[1]);
                MMA16816(oacc[db * 2 + 1], pah[ks], b_l[2], b_l[3]);
                MMA16816(oacc[db * 2 + 0], pal[ks], b_h[0], b_h[1]);
                MMA16816(oacc[db * 2 + 1], pal[ks], b_h[2], b_h[3]);
            }
        }
    }
    __syncthreads();

    float* Obuf = (float*)smc + wn * (64 * 66);
#pragma unroll
    for (int t = 0; t < 8; t++) {
        int d = t * 8 + (lane & 3) * 2;
        *(float2*)(Obuf + i_t * 66 + d) = make_float2(oacc[t][0], oacc[t][1]);
        *(float2*)(Obuf + i_b * 66 + d) = make_float2(oacc[t][2], oacc[t][3]);
    }
    __syncthreads();

    float* Ob0 = (float*)smc;
    float* Ob1 = (float*)smc + 64 * 66;
#pragma unroll
    for (int it = 0; it < 2; it++) {
        int idx = tid + it * 256;
        int row = idx >> 3, dg = (idx & 7) * 8;
        __nv_bfloat16 hh[8], ll[8];
#pragma unroll
        for (int e = 0; e < 8; e++) {
            float v = Ob0[row * 66 + dg + e] + Ob1[row * 66 + dg + e];
            split_bf16(v, hh[e], ll[e]);
        }
        long gidx = ((long)(b * S_ + s0 + row)) * DM_ + h * D_ + dg;
        *(uint4*)(g_ah + gidx) = *(uint4*)hh;
        *(uint4*)(g_al + gidx) = *(uint4*)ll;
    }
}

// ---------------------------------------------------------------------------
extern "C" void kernel_launch(void* const* d_in, const int* in_sizes, int n_in,
                              void* d_out, int out_size)
{
    const float* x  = (const float*)d_in[0];
    const float* Wq = (const float*)d_in[1];
    const float* Wk = (const float*)d_in[2];
    const float* Wv = (const float*)d_in[3];
    const float* Wo = (const float*)d_in[4];
    float* out = (float*)d_out;

    cudaFuncSetAttribute(mma_gemm_qkv, cudaFuncAttributeMaxDynamicSharedMemorySize, GSM_BYTES);
    cudaFuncSetAttribute(mma_gemm_out, cudaFuncAttributeMaxDynamicSharedMemorySize, GSM_BYTES);
    cudaFuncSetAttribute(attn_k, cudaFuncAttributeMaxDynamicSharedMemorySize, AT_BYTES);

    conv_k<<<3072, 256>>>(x, Wq, Wk, Wv, Wo);
    mma_gemm_qkv<<<dim3(12, 32), 256, GSM_BYTES>>>();
    attn_k<<<dim3(S_ / 64, H_, B_), 256, AT_BYTES>>>();
    mma_gemm_out<<<dim3(4, 32), 256, GSM_BYTES>>>(out);
}